// round 1
// baseline (speedup 1.0000x reference)
#include <cuda_runtime.h>

#define NRELS 19
#define DIM   32
#define MAXN  100000
#define MAXE  1600000

// ---------------- static scratch (no allocation allowed) ----------------
static __device__ int    g_cnt[MAXN * NRELS];      // per (node, rel) in-edge counts (layer 1)
static __device__ float  g_h1[MAXN * DIM];         // layer-1 activations
static __device__ float4 g_h2[MAXN * (DIM / 4)];   // layer-2 accumulator (16B-aligned for red.v4)
static __device__ int    g_esrc[MAXE];             // relation-bucketed edge src
static __device__ int    g_edst[MAXE];             // relation-bucketed edge dst
static __device__ int    g_relHist[NRELS];
static __device__ int    g_relOff[NRELS + 1];
static __device__ int    g_relCur[NRELS];

// ---------------- sm_103a packed-fp32 + vector-red helpers ----------------
__device__ __forceinline__ unsigned long long pack2(float lo, float hi) {
    unsigned long long r;
    asm("mov.b64 %0, {%1, %2};" : "=l"(r) : "f"(lo), "f"(hi));
    return r;
}
__device__ __forceinline__ float2 unpack2(unsigned long long v) {
    float2 r;
    asm("mov.b64 {%0, %1}, %2;" : "=f"(r.x), "=f"(r.y) : "l"(v));
    return r;
}
__device__ __forceinline__ void fma2(unsigned long long& acc, unsigned long long a,
                                     unsigned long long b) {
    asm("fma.rn.f32x2 %0, %1, %2, %0;" : "+l"(acc) : "l"(a), "l"(b));
}
__device__ __forceinline__ void red4(float* p, float a, float b, float c, float d) {
    asm volatile("red.global.add.v4.f32 [%0], {%1, %2, %3, %4};"
                 :: "l"(p), "f"(a), "f"(b), "f"(c), "f"(d) : "memory");
}

// ---------------- kernels ----------------

// Zero all per-launch accumulators (graph replays must start clean).
__global__ void k_zero(int N) {
    int stride = gridDim.x * blockDim.x;
    int tid = blockIdx.x * blockDim.x + threadIdx.x;
    for (int i = tid; i < N * NRELS; i += stride) g_cnt[i] = 0;
    float* h2 = (float*)g_h2;
    for (int i = tid; i < N * DIM; i += stride) h2[i] = 0.0f;
    if (tid < NRELS) g_relHist[tid] = 0;
}

// Per-(dst,rel) edge counts (layer-1 aggregation, exact int) + relation histogram.
__global__ void k_hist(const int* __restrict__ dst, const int* __restrict__ et, int E) {
    __shared__ int sh[NRELS];
    if (threadIdx.x < NRELS) sh[threadIdx.x] = 0;
    __syncthreads();
    int stride = gridDim.x * blockDim.x;
    for (int e = blockIdx.x * blockDim.x + threadIdx.x; e < E; e += stride) {
        int r = et[e];
        int d = dst[e];
        atomicAdd(&g_cnt[d * NRELS + r], 1);
        atomicAdd(&sh[r], 1);
    }
    __syncthreads();
    if (threadIdx.x < NRELS) atomicAdd(&g_relHist[threadIdx.x], sh[threadIdx.x]);
}

// 19-element exclusive scan (trivial, single thread).
__global__ void k_scan() {
    if (threadIdx.x == 0) {
        int s = 0;
        for (int r = 0; r < NRELS; r++) {
            g_relOff[r] = s;
            g_relCur[r] = s;
            s += g_relHist[r];
        }
        g_relOff[NRELS] = s;
    }
}

// Counting-sort scatter by relation, block-aggregated cursor reservation
// (avoids 1.6M global atomics on 19 hot counters).
__global__ void k_scatter(const int* __restrict__ src, const int* __restrict__ dst,
                          const int* __restrict__ et, int E) {
    __shared__ int shCnt[NRELS];
    __shared__ int shBase[NRELS];
    int t = threadIdx.x;
    for (int base = blockIdx.x * blockDim.x; base < E; base += gridDim.x * blockDim.x) {
        int e = base + t;
        if (t < NRELS) shCnt[t] = 0;
        __syncthreads();
        int r = 0, lp = 0, s = 0, d = 0;
        if (e < E) {
            r = et[e]; s = src[e]; d = dst[e];
            lp = atomicAdd(&shCnt[r], 1);
        }
        __syncthreads();
        if (t < NRELS) shBase[t] = atomicAdd(&g_relCur[t], shCnt[t]);
        __syncthreads();
        if (e < E) {
            int p = shBase[r] + lp;
            g_esrc[p] = s;
            g_edst[p] = d;
        }
        __syncthreads();
    }
}

// Layer 1: h1[v,o] = relu(b1[o] + sum_r cnt[v,r] * W1[r,o]).  Warp per node.
__global__ void k_layer1(const float* __restrict__ W1, const float* __restrict__ b1, int N) {
    __shared__ float sW[NRELS * DIM];
    __shared__ float sb[DIM];
    int t = threadIdx.x;
    for (int i = t; i < NRELS * DIM; i += blockDim.x) sW[i] = W1[i];
    if (t < DIM) sb[t] = b1[t];
    __syncthreads();
    int lane = t & 31;
    int wpb = blockDim.x >> 5;
    for (int v = blockIdx.x * wpb + (t >> 5); v < N; v += gridDim.x * wpb) {
        const int* crow = &g_cnt[v * NRELS];
        float acc = sb[lane];
#pragma unroll
        for (int r = 0; r < NRELS; r++)
            acc += (float)__ldg(&crow[r]) * sW[r * DIM + lane];
        g_h1[v * DIM + lane] = fmaxf(acc, 0.0f);
    }
}

// Layer 2 (the hot kernel): fused per-edge GEMV with W2[rel] register-resident
// per warp (lane = output column, 16 packed f32x2 pairs over the reduction dim),
// h1[src] staged to SMEM and read back as broadcast LDS.128, result scattered
// with red.global.add.v4.f32 into the L2-resident accumulator.
__global__ void __launch_bounds__(256) k_layer2(const float* __restrict__ W2, int E, int nWarps) {
    __shared__ float4 shh[8][8];
    __shared__ int sOff[NRELS + 1];
    int t = threadIdx.x;
    if (t <= NRELS) sOff[t] = g_relOff[t];
    __syncthreads();
    int lane = t & 31;
    int warp = t >> 5;
    float* myh = (float*)&shh[warp][0];

    int gw = blockIdx.x * 8 + warp;
    if (gw >= nWarps) return;
    int e    = (int)(((long long)gw * E) / nWarps);
    int eEnd = (int)(((long long)(gw + 1) * E) / nWarps);

    int r = 0;
    while (e < eEnd) {
        while (sOff[r + 1] <= e) r++;               // edges are relation-sorted
        int runEnd = min(eEnd, sOff[r + 1]);
        const float* Wr = W2 + r * DIM * DIM;
        unsigned long long w[16];
#pragma unroll
        for (int i = 0; i < 16; i++) {
            float lo = __ldg(&Wr[(2 * i) * DIM + lane]);
            float hi = __ldg(&Wr[(2 * i + 1) * DIM + lane]);
            w[i] = pack2(lo, hi);
        }
        for (; e < runEnd; e++) {
            int s = __ldg(&g_esrc[e]);
            int d = __ldg(&g_edst[e]);
            myh[lane] = __ldg(&g_h1[s * DIM + lane]);   // coalesced 128B gather (L2-hot)
            __syncwarp();
            unsigned long long acc = 0ull;
#pragma unroll
            for (int j = 0; j < 8; j++) {
                float4 hv = shh[warp][j];               // broadcast LDS.128
                fma2(acc, pack2(hv.x, hv.y), w[2 * j]);
                fma2(acc, pack2(hv.z, hv.w), w[2 * j + 1]);
            }
            __syncwarp();
            float2 a2 = unpack2(acc);
            float accf = a2.x + a2.y;
            int srcl = (lane & 7) * 4;
            float v0 = __shfl_sync(0xffffffffu, accf, srcl + 0);
            float v1 = __shfl_sync(0xffffffffu, accf, srcl + 1);
            float v2 = __shfl_sync(0xffffffffu, accf, srcl + 2);
            float v3 = __shfl_sync(0xffffffffu, accf, srcl + 3);
            if (lane < 8) {
                float* p = ((float*)g_h2) + (size_t)d * DIM + lane * 4;
                red4(p, v0, v1, v2, v3);                // 16B vector reduction
            }
        }
    }
}

// Final: out[v] = relu(h2acc[v] + b2) @ W3 + b3.  Warp per node, shfl-broadcast h.
__global__ void k_final(const float* __restrict__ W3, const float* __restrict__ b2,
                        const float* __restrict__ b3, float* __restrict__ out, int N) {
    __shared__ float sW[DIM * DIM];
    __shared__ float sb2[DIM];
    __shared__ float sb3[DIM];
    int t = threadIdx.x;
    for (int i = t; i < DIM * DIM; i += blockDim.x) sW[i] = W3[i];
    if (t < DIM) { sb2[t] = b2[t]; sb3[t] = b3[t]; }
    __syncthreads();
    int lane = t & 31;
    int wpb = blockDim.x >> 5;
    for (int v = blockIdx.x * wpb + (t >> 5); v < N; v += gridDim.x * wpb) {
        float h = fmaxf(((const float*)g_h2)[v * DIM + lane] + sb2[lane], 0.0f);
        float acc = sb3[lane];
#pragma unroll
        for (int i = 0; i < DIM; i++) {
            float hi = __shfl_sync(0xffffffffu, h, i);
            acc += hi * sW[i * DIM + lane];
        }
        out[v * DIM + lane] = acc;
    }
}

// ---------------- launch ----------------
extern "C" void kernel_launch(void* const* d_in, const int* in_sizes, int n_in,
                              void* d_out, int out_size) {
    const int* src = (const int*)d_in[0];
    const int* dst = (const int*)d_in[1];
    const int* et  = (const int*)d_in[2];
    // n_nodes may or may not appear as a size-1 scalar input; detect and skip it.
    int base = (n_in > 3 && in_sizes[3] == 1) ? 4 : 3;
    const float* W1 = (const float*)d_in[base + 0];
    const float* b1 = (const float*)d_in[base + 1];
    const float* W2 = (const float*)d_in[base + 2];
    const float* b2 = (const float*)d_in[base + 3];
    const float* W3 = (const float*)d_in[base + 4];
    const float* b3 = (const float*)d_in[base + 5];

    int E = in_sizes[0];
    int N = out_size / DIM;
    float* out = (float*)d_out;

    k_zero<<<512, 256>>>(N);
    k_hist<<<1024, 256>>>(dst, et, E);
    k_scan<<<1, 32>>>();
    k_scatter<<<1024, 256>>>(src, dst, et, E);

    int nodeBlocks = (N + 7) / 8;
    k_layer1<<<nodeBlocks, 256>>>(W1, b1, N);

    const int nWarps = 4736;  // 148 SMs x 4 blocks x 8 warps -> one balanced wave
    k_layer2<<<nWarps / 8, 256>>>(W2, E, nWarps);

    k_final<<<nodeBlocks, 256>>>(W3, b2, b3, out, N);
}

// round 2
// speedup vs baseline: 1.2090x; 1.2090x over previous
#include <cuda_runtime.h>

#define NRELS 19
#define DIM   32
#define MAXN  100000
#define MAXE  1600000

// ---------------- static scratch (no allocation allowed) ----------------
static __device__ int    g_cnt[MAXN * NRELS];      // per (node, rel) in-edge counts (layer 1)
static __device__ float  g_h1[MAXN * DIM];         // layer-1 activations
static __device__ float4 g_h2[MAXN * (DIM / 4)];   // layer-2 accumulator (16B-aligned for red.v4)
static __device__ int2   g_edata[MAXE];            // relation-bucketed (src, dst)
static __device__ int    g_relHist[NRELS];
static __device__ int    g_relOff[NRELS + 1];
static __device__ int    g_relCur[NRELS];

// ---------------- sm_103a packed-fp32 + vector-red helpers ----------------
__device__ __forceinline__ unsigned long long pack2(float lo, float hi) {
    unsigned long long r;
    asm("mov.b64 %0, {%1, %2};" : "=l"(r) : "f"(lo), "f"(hi));
    return r;
}
__device__ __forceinline__ float2 unpack2(unsigned long long v) {
    float2 r;
    asm("mov.b64 {%0, %1}, %2;" : "=f"(r.x), "=f"(r.y) : "l"(v));
    return r;
}
__device__ __forceinline__ void fma2(unsigned long long& acc, unsigned long long a,
                                     unsigned long long b) {
    asm("fma.rn.f32x2 %0, %1, %2, %0;" : "+l"(acc) : "l"(a), "l"(b));
}
__device__ __forceinline__ void red4(float* p, float a, float b, float c, float d) {
    asm volatile("red.global.add.v4.f32 [%0], {%1, %2, %3, %4};"
                 :: "l"(p), "f"(a), "f"(b), "f"(c), "f"(d) : "memory");
}

// ---------------- kernels ----------------

__global__ void k_zero(int N) {
    int stride = gridDim.x * blockDim.x;
    int tid = blockIdx.x * blockDim.x + threadIdx.x;
    for (int i = tid; i < N * NRELS; i += stride) g_cnt[i] = 0;
    float* h2 = (float*)g_h2;
    for (int i = tid; i < N * DIM; i += stride) h2[i] = 0.0f;
    if (tid < NRELS) g_relHist[tid] = 0;
}

// Per-(dst,rel) counts + relation histogram, 4 edges per thread (int4 loads).
__global__ void k_hist(const int* __restrict__ dst, const int* __restrict__ et, int E) {
    __shared__ int sh[NRELS];
    if (threadIdx.x < NRELS) sh[threadIdx.x] = 0;
    __syncthreads();
    int e0 = (blockIdx.x * blockDim.x + threadIdx.x) * 4;
    if (e0 + 3 < E) {
        int4 d4 = *(const int4*)&dst[e0];
        int4 r4 = *(const int4*)&et[e0];
        atomicAdd(&g_cnt[d4.x * NRELS + r4.x], 1);
        atomicAdd(&g_cnt[d4.y * NRELS + r4.y], 1);
        atomicAdd(&g_cnt[d4.z * NRELS + r4.z], 1);
        atomicAdd(&g_cnt[d4.w * NRELS + r4.w], 1);
        atomicAdd(&sh[r4.x], 1); atomicAdd(&sh[r4.y], 1);
        atomicAdd(&sh[r4.z], 1); atomicAdd(&sh[r4.w], 1);
    } else {
        for (int e = e0; e < E; e++) {
            int r = et[e];
            atomicAdd(&g_cnt[dst[e] * NRELS + r], 1);
            atomicAdd(&sh[r], 1);
        }
    }
    __syncthreads();
    if (threadIdx.x < NRELS) atomicAdd(&g_relHist[threadIdx.x], sh[threadIdx.x]);
}

__global__ void k_scan() {
    if (threadIdx.x == 0) {
        int s = 0;
        for (int r = 0; r < NRELS; r++) {
            g_relOff[r] = s;
            g_relCur[r] = s;
            s += g_relHist[r];
        }
        g_relOff[NRELS] = s;
    }
}

// Counting-sort scatter by relation, 4 edges/thread, block-aggregated cursors.
__global__ void k_scatter(const int* __restrict__ src, const int* __restrict__ dst,
                          const int* __restrict__ et, int E) {
    __shared__ int shCnt[NRELS];
    __shared__ int shBase[NRELS];
    int t = threadIdx.x;
    if (t < NRELS) shCnt[t] = 0;
    __syncthreads();
    int e0 = (blockIdx.x * blockDim.x + t) * 4;
    int r[4], s[4], d[4], lp[4];
    int cnt = 0;
    if (e0 + 3 < E) {
        int4 s4 = *(const int4*)&src[e0];
        int4 d4 = *(const int4*)&dst[e0];
        int4 r4 = *(const int4*)&et[e0];
        s[0]=s4.x; s[1]=s4.y; s[2]=s4.z; s[3]=s4.w;
        d[0]=d4.x; d[1]=d4.y; d[2]=d4.z; d[3]=d4.w;
        r[0]=r4.x; r[1]=r4.y; r[2]=r4.z; r[3]=r4.w;
        cnt = 4;
    } else {
        for (int e = e0; e < E; e++) {
            s[cnt]=src[e]; d[cnt]=dst[e]; r[cnt]=et[e]; cnt++;
        }
    }
    for (int k = 0; k < cnt; k++) lp[k] = atomicAdd(&shCnt[r[k]], 1);
    __syncthreads();
    if (t < NRELS) shBase[t] = atomicAdd(&g_relCur[t], shCnt[t]);
    __syncthreads();
    for (int k = 0; k < cnt; k++)
        g_edata[shBase[r[k]] + lp[k]] = make_int2(s[k], d[k]);
}

// Layer 1: h1[v,o] = relu(b1[o] + sum_r cnt[v,r] * W1[r,o]).  Warp per node.
__global__ void k_layer1(const float* __restrict__ W1, const float* __restrict__ b1, int N) {
    __shared__ float sW[NRELS * DIM];
    __shared__ float sb[DIM];
    int t = threadIdx.x;
    for (int i = t; i < NRELS * DIM; i += blockDim.x) sW[i] = W1[i];
    if (t < DIM) sb[t] = b1[t];
    __syncthreads();
    int lane = t & 31;
    int wpb = blockDim.x >> 5;
    for (int v = blockIdx.x * wpb + (t >> 5); v < N; v += gridDim.x * wpb) {
        const int* crow = &g_cnt[v * NRELS];
        float acc = sb[lane];
#pragma unroll
        for (int r = 0; r < NRELS; r++)
            acc += (float)__ldg(&crow[r]) * sW[r * DIM + lane];
        g_h1[v * DIM + lane] = fmaxf(acc, 0.0f);
    }
}

// Layer 2 (hot): per warp, 4 edges per iteration.
//  - W2[rel] register-resident (16 f32x2 per lane, lane = output column)
//  - 4 independent h-gather LDGs per batch + software prefetch of next batch
//  - 4 interleaved fma2 accumulator chains (ILP instead of pure occupancy)
//  - reduction: SMEM transpose (4 STS + 1 LDS.128) then ONE red.global.add.v4
//    covering all 4 edges. Tail edges padded with h=0 -> exact zero adds.
__global__ void __launch_bounds__(128, 5) k_layer2(const float* __restrict__ W2,
                                                   int E, int nWarps) {
    __shared__ float shh[4][4][DIM];   // [warp][edge-in-batch][i]
    __shared__ float sacc[4][4][DIM];  // [warp][edge-in-batch][col]
    __shared__ int sOff[NRELS + 1];
    int t = threadIdx.x;
    if (t <= NRELS) sOff[t] = g_relOff[t];
    __syncthreads();
    int lane = t & 31;
    int warp = t >> 5;
    int grp  = lane >> 3;          // edge index for the reduction wave
    int cg4  = (lane & 7) * 4;     // column group for the reduction wave

    int gw = blockIdx.x * 4 + warp;
    if (gw >= nWarps) return;
    int e    = (int)(((long long)gw * E) / nWarps);
    int eEnd = (int)(((long long)(gw + 1) * E) / nWarps);

    int r = 0;
    while (e < eEnd) {
        while (sOff[r + 1] <= e) r++;               // edges are relation-sorted
        int runEnd = min(eEnd, sOff[r + 1]);
        if (e < runEnd) {
            const float* Wr = W2 + r * DIM * DIM;
            unsigned long long w[16];
#pragma unroll
            for (int i = 0; i < 16; i++) {
                float lo = __ldg(&Wr[(2 * i) * DIM + lane]);
                float hi = __ldg(&Wr[(2 * i + 1) * DIM + lane]);
                w[i] = pack2(lo, hi);
            }

            // prime batch 0
            int d0, d1, d2, d3;
            float h0, h1, h2, h3;
            {
                int2 ed;
                ed = __ldg(&g_edata[e]);
                d0 = ed.y; h0 = __ldg(&g_h1[ed.x * DIM + lane]);
                bool a1 = e + 1 < runEnd, a2 = e + 2 < runEnd, a3 = e + 3 < runEnd;
                ed = a1 ? __ldg(&g_edata[e + 1]) : make_int2(0, 0);
                d1 = ed.y; h1 = a1 ? __ldg(&g_h1[ed.x * DIM + lane]) : 0.0f;
                ed = a2 ? __ldg(&g_edata[e + 2]) : make_int2(0, 0);
                d2 = ed.y; h2 = a2 ? __ldg(&g_h1[ed.x * DIM + lane]) : 0.0f;
                ed = a3 ? __ldg(&g_edata[e + 3]) : make_int2(0, 0);
                d3 = ed.y; h3 = a3 ? __ldg(&g_h1[ed.x * DIM + lane]) : 0.0f;
            }

            for (int eb = e; eb < runEnd; eb += 4) {
                // stage current batch's h
                shh[warp][0][lane] = h0;
                shh[warp][1][lane] = h1;
                shh[warp][2][lane] = h2;
                shh[warp][3][lane] = h3;
                int dd0 = d0, dd1 = d1, dd2 = d2, dd3 = d3;
                __syncwarp();

                // prefetch next batch (overlaps compute below)
                int en = eb + 4;
                if (en < runEnd) {
                    int2 ed;
                    ed = __ldg(&g_edata[en]);
                    d0 = ed.y; h0 = __ldg(&g_h1[ed.x * DIM + lane]);
                    bool a1 = en + 1 < runEnd, a2 = en + 2 < runEnd, a3 = en + 3 < runEnd;
                    ed = a1 ? __ldg(&g_edata[en + 1]) : make_int2(0, 0);
                    d1 = ed.y; h1 = a1 ? __ldg(&g_h1[ed.x * DIM + lane]) : 0.0f;
                    ed = a2 ? __ldg(&g_edata[en + 2]) : make_int2(0, 0);
                    d2 = ed.y; h2 = a2 ? __ldg(&g_h1[ed.x * DIM + lane]) : 0.0f;
                    ed = a3 ? __ldg(&g_edata[en + 3]) : make_int2(0, 0);
                    d3 = ed.y; h3 = a3 ? __ldg(&g_h1[ed.x * DIM + lane]) : 0.0f;
                }

                // 4 interleaved GEMV chains
                unsigned long long ac0 = 0ull, ac1 = 0ull, ac2 = 0ull, ac3 = 0ull;
#pragma unroll
                for (int j = 0; j < 8; j++) {
                    float4 v0 = *(const float4*)&shh[warp][0][j * 4];
                    float4 v1 = *(const float4*)&shh[warp][1][j * 4];
                    float4 v2 = *(const float4*)&shh[warp][2][j * 4];
                    float4 v3 = *(const float4*)&shh[warp][3][j * 4];
                    fma2(ac0, pack2(v0.x, v0.y), w[2 * j]);
                    fma2(ac1, pack2(v1.x, v1.y), w[2 * j]);
                    fma2(ac2, pack2(v2.x, v2.y), w[2 * j]);
                    fma2(ac3, pack2(v3.x, v3.y), w[2 * j]);
                    fma2(ac0, pack2(v0.z, v0.w), w[2 * j + 1]);
                    fma2(ac1, pack2(v1.z, v1.w), w[2 * j + 1]);
                    fma2(ac2, pack2(v2.z, v2.w), w[2 * j + 1]);
                    fma2(ac3, pack2(v3.z, v3.w), w[2 * j + 1]);
                }
                float2 a;
                a = unpack2(ac0); sacc[warp][0][lane] = a.x + a.y;
                a = unpack2(ac1); sacc[warp][1][lane] = a.x + a.y;
                a = unpack2(ac2); sacc[warp][2][lane] = a.x + a.y;
                a = unpack2(ac3); sacc[warp][3][lane] = a.x + a.y;
                __syncwarp();

                // one vector reduction for all 4 edges: lane grp owns edge grp, cols cg4..cg4+3
                float4 v = *(const float4*)&sacc[warp][grp][cg4];
                int dsel = (grp == 0) ? dd0 : (grp == 1) ? dd1 : (grp == 2) ? dd2 : dd3;
                red4(((float*)g_h2) + (size_t)dsel * DIM + cg4, v.x, v.y, v.z, v.w);
            }
            e = runEnd;
        }
    }
}

// Final: out[v] = relu(h2acc[v] + b2) @ W3 + b3.  Warp per node, shfl-broadcast h.
__global__ void k_final(const float* __restrict__ W3, const float* __restrict__ b2,
                        const float* __restrict__ b3, float* __restrict__ out, int N) {
    __shared__ float sW[DIM * DIM];
    __shared__ float sb2[DIM];
    __shared__ float sb3[DIM];
    int t = threadIdx.x;
    for (int i = t; i < DIM * DIM; i += blockDim.x) sW[i] = W3[i];
    if (t < DIM) { sb2[t] = b2[t]; sb3[t] = b3[t]; }
    __syncthreads();
    int lane = t & 31;
    int wpb = blockDim.x >> 5;
    for (int v = blockIdx.x * wpb + (t >> 5); v < N; v += gridDim.x * wpb) {
        float h = fmaxf(((const float*)g_h2)[v * DIM + lane] + sb2[lane], 0.0f);
        float acc = sb3[lane];
#pragma unroll
        for (int i = 0; i < DIM; i++) {
            float hi = __shfl_sync(0xffffffffu, h, i);
            acc += hi * sW[i * DIM + lane];
        }
        out[v * DIM + lane] = acc;
    }
}

// ---------------- launch ----------------
extern "C" void kernel_launch(void* const* d_in, const int* in_sizes, int n_in,
                              void* d_out, int out_size) {
    const int* src = (const int*)d_in[0];
    const int* dst = (const int*)d_in[1];
    const int* et  = (const int*)d_in[2];
    int base = (n_in > 3 && in_sizes[3] == 1) ? 4 : 3;
    const float* W1 = (const float*)d_in[base + 0];
    const float* b1 = (const float*)d_in[base + 1];
    const float* W2 = (const float*)d_in[base + 2];
    const float* b2 = (const float*)d_in[base + 3];
    const float* W3 = (const float*)d_in[base + 4];
    const float* b3 = (const float*)d_in[base + 5];

    int E = in_sizes[0];
    int N = out_size / DIM;
    float* out = (float*)d_out;

    k_zero<<<1024, 256>>>(N);
    int edgeBlocks4 = (E / 4 + 255) / 256 + 1;
    k_hist<<<edgeBlocks4, 256>>>(dst, et, E);
    k_scan<<<1, 32>>>();
    k_scatter<<<edgeBlocks4, 256>>>(src, dst, et, E);

    int nodeBlocks = (N + 7) / 8;
    k_layer1<<<nodeBlocks, 256>>>(W1, b1, N);

    const int nWarps = 2960;   // 148 SMs x 5 blocks x 4 warps -> one balanced wave
    k_layer2<<<nWarps / 4, 128>>>(W2, E, nWarps);

    k_final<<<nodeBlocks, 256>>>(W3, b2, b3, out, N);
}